// round 16
// baseline (speedup 1.0000x reference)
#include <cuda_runtime.h>
#include <cuda_fp16.h>
#include <cstdint>

#define BB 2
#define TT 2048
#define NH 12
#define DH 64
#define DM 768
#define NQKV (3*DM)
#define MROWS (BB*TT)   // 4096

// Scratch (allocation-free). NOTE: never pass these symbols from host code —
// GB300 ATS silently resolves the host shadow address (reads zeros).
__device__ __align__(16) __half g_xh [(size_t)MROWS*DM];
__device__ __align__(16) __half g_xl [(size_t)MROWS*DM];
__device__ __align__(16) __half g_wat[(size_t)NQKV*DM];   // [2304,768] transposed, f16
__device__ __align__(16) __half g_wpt[(size_t)DM*DM];     // [768,768]  transposed, f16
__device__ __align__(16) __half g_qh[(size_t)BB*NH*TT*DH];  // q hi (scaled)
__device__ __align__(16) __half g_ql[(size_t)BB*NH*TT*DH];  // q lo
__device__ __align__(16) __half g_k [(size_t)BB*NH*TT*DH];  // k single f16
__device__ __align__(16) __half g_vt[(size_t)BB*NH*DH*TT];  // v single f16 [B,H,D,T]
__device__ __align__(16) __half g_yh[(size_t)MROWS*DM];
__device__ __align__(16) __half g_yl[(size_t)MROWS*DM];

// ---------------- helpers ----------------------------------------------------------
__device__ __forceinline__ void split_h(float v, __half& hi, __half& lo)
{
    hi = __float2half_rn(v);
    lo = __float2half_rn(v - __half2float(hi));
}

__device__ __forceinline__ void mma16816h(float* c, uint32_t a0, uint32_t a1,
                                          uint32_t a2, uint32_t a3,
                                          uint32_t b0, uint32_t b1)
{
    asm volatile(
        "mma.sync.aligned.m16n8k16.row.col.f32.f16.f16.f32 "
        "{%0,%1,%2,%3}, {%4,%5,%6,%7}, {%8,%9}, {%0,%1,%2,%3};\n"
        : "+f"(c[0]), "+f"(c[1]), "+f"(c[2]), "+f"(c[3])
        : "r"(a0), "r"(a1), "r"(a2), "r"(a3), "r"(b0), "r"(b1));
}

__device__ __forceinline__ uint32_t lds32(const __half* p)
{
    return *(const uint32_t*)p;
}

__device__ __forceinline__ void packsplit_h(float x, float y, uint32_t& hi, uint32_t& lo)
{
    __half2 h = __floats2half2_rn(x, y);
    float2 hf = __half22float2(h);
    __half2 l = __floats2half2_rn(x - hf.x, y - hf.y);
    hi = *(uint32_t*)&h;
    lo = *(uint32_t*)&l;
}

__device__ __forceinline__ void cp16(void* smem_ptr, const void* gptr)
{
    uint32_t sa = (uint32_t)__cvta_generic_to_shared(smem_ptr);
    asm volatile("cp.async.cg.shared.global [%0], [%1], 16;\n"
                 :: "r"(sa), "l"(gptr));
}
#define CP_COMMIT() asm volatile("cp.async.commit_group;\n" ::: "memory")
#define CP_WAIT1()  asm volatile("cp.async.wait_group 1;\n" ::: "memory")
#define CP_WAIT0()  asm volatile("cp.async.wait_group 0;\n" ::: "memory")

// ---------------- input split kernels ----------------------------------------------
__global__ __launch_bounds__(256) void split_x(const float* __restrict__ x)
{
    size_t i = ((size_t)blockIdx.x * 256 + threadIdx.x) * 8;
    float4 v0 = *(const float4*)(x + i);
    float4 v1 = *(const float4*)(x + i + 4);
    float vv[8] = {v0.x, v0.y, v0.z, v0.w, v1.x, v1.y, v1.z, v1.w};
    __half h[8], l[8];
#pragma unroll
    for (int j = 0; j < 8; j++) split_h(vv[j], h[j], l[j]);
    *(uint4*)(g_xh + i) = *(uint4*)h;
    *(uint4*)(g_xl + i) = *(uint4*)l;
}

// Transpose weight [768, N] -> [N, 768] single f16.  W=0: w_attn, W=1: w_proj
template <int W>
__global__ __launch_bounds__(256) void splitT_w(const float* __restrict__ w, int N)
{
    __shared__ float ts[32][33];
    const int tx = threadIdx.x & 31, ty = threadIdx.x >> 5;  // 32 x 8
    const int n0 = blockIdx.x * 32, k0 = blockIdx.y * 32;
#pragma unroll
    for (int i = 0; i < 4; i++) {
        int ky = ty + i * 8;
        ts[ky][tx] = w[(size_t)(k0 + ky) * N + n0 + tx];
    }
    __syncthreads();
    __half* th = (W == 0) ? g_wat : g_wpt;
#pragma unroll
    for (int i = 0; i < 4; i++) {
        int r = ty + i * 8;
        th[(size_t)(n0 + r) * DM + k0 + tx] = __float2half_rn(ts[tx][r]);
    }
}

// ---------------- 2-term f16 raw-mma GEMM, cp.async double-buffered -----------------
// (unchanged from R15)
#define GM 128
#define GN 128
#define GKT 32
#define GLD 40
#define GCN 68
#define GST (3*GM*GLD)
#define GEMM_SMEM (2*GST*2 > GM*GCN*4 ? 2*GST*2 : GM*GCN*4)   // 61440 B

template <int MODE>
__global__ __launch_bounds__(256) void gemm_h(const float* __restrict__ bias,
                                              float* __restrict__ Cout, int N)
{
    constexpr int K = DM;
    const __half* __restrict__ Ah = (MODE == 1) ? g_xh : g_yh;
    const __half* __restrict__ Al = (MODE == 1) ? g_xl : g_yl;
    const __half* __restrict__ Bh = (MODE == 1) ? g_wat : g_wpt;

    extern __shared__ char gsm[];
    __half* ST = (__half*)gsm;
    float*  Cs = (float*)gsm;

    const int tid  = threadIdx.x;
    const int warp = tid >> 5, lane = tid & 31;
    const int g = lane >> 2, t = lane & 3;
    const int m0 = (warp & 3) * 32, wn = warp >> 2, n0 = wn * 64;
    const int bm = blockIdx.y * GM, bn = blockIdx.x * GN;

    const int ldr  = tid >> 2;
    const int ldc8 = (tid & 3) * 8;

    auto issue = [&](int k0, int s) {
        __half* AH = ST + s * GST;
        __half* AL = AH + GM * GLD;
        __half* BH = AL + GM * GLD;
#pragma unroll
        for (int i = 0; i < 2; i++) {
            int r = ldr + i * 64;
            cp16(AH + r * GLD + ldc8, Ah + (size_t)(bm + r) * K + k0 + ldc8);
            cp16(AL + r * GLD + ldc8, Al + (size_t)(bm + r) * K + k0 + ldc8);
            cp16(BH + r * GLD + ldc8, Bh + (size_t)(bn + r) * K + k0 + ldc8);
        }
    };

    float acc[2][8][4] = {};

    issue(0, 0);
    CP_COMMIT();

    const int nk = K / GKT;   // 24
    for (int kt = 0; kt < nk; kt++) {
        if (kt + 1 < nk) { issue((kt + 1) * GKT, (kt + 1) & 1); CP_COMMIT(); CP_WAIT1(); }
        else             { CP_WAIT0(); }
        __syncthreads();

        const __half* AH = ST + (kt & 1) * GST;
        const __half* AL = AH + GM * GLD;
        const __half* BH = AL + GM * GLD;

#pragma unroll
        for (int kc = 0; kc < 2; kc++) {
            const int dlo = kc * 16 + 2 * t;
            uint32_t aH[2][4], aL[2][4];
#pragma unroll
            for (int mi = 0; mi < 2; mi++) {
                int r0 = m0 + mi * 16 + g, r1 = r0 + 8;
                aH[mi][0] = lds32(AH + r0 * GLD + dlo);
                aH[mi][1] = lds32(AH + r1 * GLD + dlo);
                aH[mi][2] = lds32(AH + r0 * GLD + dlo + 8);
                aH[mi][3] = lds32(AH + r1 * GLD + dlo + 8);
                aL[mi][0] = lds32(AL + r0 * GLD + dlo);
                aL[mi][1] = lds32(AL + r1 * GLD + dlo);
                aL[mi][2] = lds32(AL + r0 * GLD + dlo + 8);
                aL[mi][3] = lds32(AL + r1 * GLD + dlo + 8);
            }
#pragma unroll
            for (int ni = 0; ni < 8; ni++) {
                int rn = n0 + ni * 8 + g;
                uint32_t b0 = lds32(BH + rn * GLD + dlo);
                uint32_t b1 = lds32(BH + rn * GLD + dlo + 8);
#pragma unroll
                for (int mi = 0; mi < 2; mi++) {
                    mma16816h(acc[mi][ni], aH[mi][0], aH[mi][1], aH[mi][2], aH[mi][3], b0, b1);
                    mma16816h(acc[mi][ni], aL[mi][0], aL[mi][1], aL[mi][2], aL[mi][3], b0, b1);
                }
            }
        }
        __syncthreads();
    }

    // Epilogue: two 64-col passes through Cs
#pragma unroll
    for (int pass = 0; pass < 2; pass++) {
        __syncthreads();
        if (wn == pass) {
#pragma unroll
            for (int mi = 0; mi < 2; mi++)
#pragma unroll
                for (int ni = 0; ni < 8; ni++) {
                    int r = m0 + mi * 16 + g, c = ni * 8 + 2 * t;
                    *(float2*)&Cs[r * GCN + c]       = make_float2(acc[mi][ni][0], acc[mi][ni][1]);
                    *(float2*)&Cs[(r + 8) * GCN + c] = make_float2(acc[mi][ni][2], acc[mi][ni][3]);
                }
        }
        __syncthreads();

        const int nwin = bn + pass * 64;
        if (MODE == 2) {
#pragma unroll
            for (int it = 0; it < 32; it++) {
                int idx = tid + it * 256;
                int r = idx >> 6;
                int n_loc = idx & 63;
                Cout[(size_t)(bm + r) * N + nwin + n_loc] = Cs[r * GCN + n_loc] + bias[nwin + n_loc];
            }
        } else {
            const int which = nwin / DM;
            const int hd    = nwin % DM;
            const int h     = hd / DH;
            const int b     = bm / TT;
            const int t0    = bm % TT;
            const int bh    = b * NH + h;

            if (which == 2) {
#pragma unroll
                for (int it = 0; it < 4; it++) {
                    int cid = tid + it * 256;
                    int d   = cid >> 4;
                    int tc  = (cid & 15) * 8;
                    float bval = bias[nwin + d];
                    __half hb[8];
#pragma unroll
                    for (int j = 0; j < 8; j++)
                        hb[j] = __float2half_rn(Cs[(tc + j) * GCN + d] + bval);
                    *(uint4*)(g_vt + ((size_t)bh * DH + d) * TT + t0 + tc) = *(uint4*)hb;
                }
            } else if (which == 1) {
#pragma unroll
                for (int it = 0; it < 4; it++) {
                    int cid = tid + it * 256;
                    int r   = cid >> 3;
                    int c8  = (cid & 7) * 8;
                    __half hb[8];
#pragma unroll
                    for (int j = 0; j < 8; j++)
                        hb[j] = __float2half_rn(Cs[r * GCN + c8 + j] + bias[nwin + c8 + j]);
                    *(uint4*)(g_k + ((size_t)bh * TT + t0 + r) * DH + c8) = *(uint4*)hb;
                }
            } else {
#pragma unroll
                for (int it = 0; it < 4; it++) {
                    int cid = tid + it * 256;
                    int r   = cid >> 3;
                    int c8  = (cid & 7) * 8;
                    __half hb[8], lb[8];
#pragma unroll
                    for (int j = 0; j < 8; j++) {
                        float v = (Cs[r * GCN + c8 + j] + bias[nwin + c8 + j]) * 0.125f;
                        split_h(v, hb[j], lb[j]);
                    }
                    size_t dst = ((size_t)bh * TT + t0 + r) * DH + c8;
                    *(uint4*)(g_qh + dst) = *(uint4*)hb;
                    *(uint4*)(g_ql + dst) = *(uint4*)lb;
                }
            }
        }
    }
}

// ---------------- Flash attention: 128 queries/block, 8 warps, K/V pipelined --------
#define LOG2E 1.4426950408889634f
#define LDSB 72
#define QROWS 128
// smem: QH, QL (128 rows, resident) + 2 stages of (KH, VT) (64 rows each)
#define AST (2*64*LDSB)                           // halves per stage = 9216
#define ATT_SMEM ((2*QROWS*LDSB + 2*AST) * 2)     // 73728 B

__device__ __forceinline__ float fexp2(float t)   // t <= 0; returns 2^t
{
    t = fmaxf(t, -126.f);
    float fl = floorf(t);
    float x = (t - fl) * 0.69314718056f;
    float p = 1.f + x*(1.f + x*(0.5f + x*(0.16666667f + x*(0.041666667f
              + x*(0.0083333333f + x*0.0013888889f)))));
    return __int_as_float(__float_as_int(p) + ((int)fl << 23));
}

__global__ __launch_bounds__(256) void attn_reg()
{
    extern __shared__ __half smb[];
    __half* QH = smb;
    __half* QL = QH + QROWS*LDSB;
    __half* S0 = QL + QROWS*LDSB;     // K/V stage base

    const int bh   = blockIdx.y;
    const int qt   = gridDim.x - 1 - blockIdx.x;  // heavy first
    const int tid  = threadIdx.x;
    const int warp = tid >> 5;        // 0..7
    const int lane = tid & 31;
    const int g    = lane >> 2;
    const int t    = lane & 3;
    const int q0   = qt * QROWS;

    const __half* gqh = g_qh + (size_t)bh * TT * DH;
    const __half* gql = g_ql + (size_t)bh * TT * DH;
    const __half* gk  = g_k  + (size_t)bh * TT * DH;
    const __half* gv  = g_vt + (size_t)bh * DH * TT;

    auto issue_kv = [&](int kt, int s) {
        __half* KH = S0 + s * AST;
        __half* VT = KH + 64 * LDSB;
#pragma unroll
        for (int it = 0; it < 2; it++) {
            int cid = tid + it * 256;      // 0..511
            int r   = cid >> 3;            // 0..63
            int c8  = (cid & 7) * 8;
            cp16(KH + r * LDSB + c8, gk + (size_t)(kt*64 + r) * DH + c8);
            cp16(VT + r * LDSB + c8, gv + (size_t)r * TT + kt*64 + c8);
        }
    };

    issue_kv(0, 0);
    CP_COMMIT();

    // Load Q tile (128 rows) hi/lo
#pragma unroll
    for (int it = 0; it < 4; it++) {
        int cid = tid + it * 256;          // 0..1023
        int r   = cid >> 3;                // 0..127
        int c8  = (cid & 7) * 8;
        *(uint4*)(QH + r * LDSB + c8) = *(const uint4*)(gqh + (size_t)(q0 + r) * DH + c8);
        *(uint4*)(QL + r * LDSB + c8) = *(const uint4*)(gql + (size_t)(q0 + r) * DH + c8);
    }
    __syncthreads();

    // Hoist Q fragments into registers (block-invariant across kt)
    uint32_t qfh[4][4], qfl[4][4];
    {
        const int qrow = warp * 16 + g;
#pragma unroll
        for (int kc = 0; kc < 4; kc++) {
            const int dlo = kc * 16 + 2 * t;
            qfh[kc][0] = lds32(QH + qrow * LDSB + dlo);
            qfh[kc][1] = lds32(QH + (qrow + 8) * LDSB + dlo);
            qfh[kc][2] = lds32(QH + qrow * LDSB + dlo + 8);
            qfh[kc][3] = lds32(QH + (qrow + 8) * LDSB + dlo + 8);
            qfl[kc][0] = lds32(QL + qrow * LDSB + dlo);
            qfl[kc][1] = lds32(QL + (qrow + 8) * LDSB + dlo);
            qfl[kc][2] = lds32(QL + qrow * LDSB + dlo + 8);
            qfl[kc][3] = lds32(QL + (qrow + 8) * LDSB + dlo + 8);
        }
    }

    float o[8][4];
#pragma unroll
    for (int nt = 0; nt < 8; nt++)
#pragma unroll
        for (int e = 0; e < 4; e++) o[nt][e] = 0.f;
    float m0 = -1e30f, m1 = -1e30f, l0 = 0.f, l1 = 0.f;

    const int rowg  = q0 + warp * 16 + g;
    const int rowg8 = rowg + 8;
    const int ntiles = 2 * qt + 2;     // covers keys 0 .. q0+127

    for (int kt = 0; kt < ntiles; kt++) {
        if (kt + 1 < ntiles) { issue_kv(kt + 1, (kt + 1) & 1); CP_COMMIT(); CP_WAIT1(); }
        else                 { CP_WAIT0(); }
        __syncthreads();

        const __half* KH = S0 + (kt & 1) * AST;
        const __half* VT = KH + 64 * LDSB;

        // ---- S = Q K^T ----
        float s[8][4];
#pragma unroll
        for (int nt = 0; nt < 8; nt++)
#pragma unroll
            for (int e = 0; e < 4; e++) s[nt][e] = 0.f;

#pragma unroll
        for (int kc = 0; kc < 4; kc++) {
            const int dlo = kc * 16 + 2 * t;
#pragma unroll
            for (int nt = 0; nt < 8; nt++) {
                const int krow = nt * 8 + g;
                uint32_t b0 = lds32(KH + krow * LDSB + dlo);
                uint32_t b1 = lds32(KH + krow * LDSB + dlo + 8);
                mma16816h(s[nt], qfh[kc][0], qfh[kc][1], qfh[kc][2], qfh[kc][3], b0, b1);
                mma16816h(s[nt], qfl[kc][0], qfl[kc][1], qfl[kc][2], qfl[kc][3], b0, b1);
            }
        }

        // ---- causal mask (only the two diagonal-straddling tiles need it) ----
        if (kt >= ntiles - 2) {
#pragma unroll
            for (int nt = 0; nt < 8; nt++) {
                int c0 = kt * 64 + nt * 8 + 2 * t;
                if (c0     > rowg)  s[nt][0] = -1e30f;
                if (c0 + 1 > rowg)  s[nt][1] = -1e30f;
                if (c0     > rowg8) s[nt][2] = -1e30f;
                if (c0 + 1 > rowg8) s[nt][3] = -1e30f;
            }
        }

        // ---- online softmax ----
        float tmax0 = -1e30f, tmax1 = -1e30f;
#pragma unroll
        for (int nt = 0; nt < 8; nt++) {
            tmax0 = fmaxf(tmax0, fmaxf(s[nt][0], s[nt][1]));
            tmax1 = fmaxf(tmax1, fmaxf(s[nt][2], s[nt][3]));
        }
        tmax0 = fmaxf(tmax0, __shfl_xor_sync(0xffffffff, tmax0, 1));
        tmax0 = fmaxf(tmax0, __shfl_xor_sync(0xffffffff, tmax0, 2));
        tmax1 = fmaxf(tmax1, __shfl_xor_sync(0xffffffff, tmax1, 1));
        tmax1 = fmaxf(tmax1, __shfl_xor_sync(0xffffffff, tmax1, 2));

        float mnew0 = fmaxf(m0, tmax0);
        float mnew1 = fmaxf(m1, tmax1);
        float f0 = fexp2((m0 - mnew0) * LOG2E);
        float f1 = fexp2((m1 - mnew1) * LOG2E);

        uint32_t pah[4][4], pal[4][4];
        float ls0 = 0.f, ls1 = 0.f;
#pragma unroll
        for (int kc = 0; kc < 4; kc++) {
            float p00 = fexp2((s[2*kc][0]   - mnew0) * LOG2E);
            float p01 = fexp2((s[2*kc][1]   - mnew0) * LOG2E);
            float p02 = fexp2((s[2*kc][2]   - mnew1) * LOG2E);
            float p03 = fexp2((s[2*kc][3]   - mnew1) * LOG2E);
            float p10 = fexp2((s[2*kc+1][0] - mnew0) * LOG2E);
            float p11 = fexp2((s[2*kc+1][1] - mnew0) * LOG2E);
            float p12 = fexp2((s[2*kc+1][2] - mnew1) * LOG2E);
            float p13 = fexp2((s[2*kc+1][3] - mnew1) * LOG2E);
            packsplit_h(p00, p01, pah[kc][0], pal[kc][0]);
            packsplit_h(p02, p03, pah[kc][1], pal[kc][1]);
            packsplit_h(p10, p11, pah[kc][2], pal[kc][2]);
            packsplit_h(p12, p13, pah[kc][3], pal[kc][3]);
            ls0 += (p00 + p01) + (p10 + p11);
            ls1 += (p02 + p03) + (p12 + p13);
        }
        ls0 += __shfl_xor_sync(0xffffffff, ls0, 1);
        ls0 += __shfl_xor_sync(0xffffffff, ls0, 2);
        ls1 += __shfl_xor_sync(0xffffffff, ls1, 1);
        ls1 += __shfl_xor_sync(0xffffffff, ls1, 2);

        l0 = l0 * f0 + ls0;  m0 = mnew0;
        l1 = l1 * f1 + ls1;  m1 = mnew1;

#pragma unroll
        for (int nt = 0; nt < 8; nt++) {
            o[nt][0] *= f0; o[nt][1] *= f0;
            o[nt][2] *= f1; o[nt][3] *= f1;
        }

        // ---- O += P * V (P exact hi/lo, V single f16) ----
#pragma unroll
        for (int kc = 0; kc < 4; kc++) {
            const int klo = kc * 16 + 2 * t;
#pragma unroll
            for (int nt = 0; nt < 8; nt++) {
                const int drow = nt * 8 + g;
                uint32_t v0 = lds32(VT + drow * LDSB + klo);
                uint32_t v1 = lds32(VT + drow * LDSB + klo + 8);
                mma16816h(o[nt], pah[kc][0], pah[kc][1], pah[kc][2], pah[kc][3], v0, v1);
                mma16816h(o[nt], pal[kc][0], pal[kc][1], pal[kc][2], pal[kc][3], v0, v1);
            }
        }
        __syncthreads();
    }

    // ---- epilogue: normalize, split f16 hi/lo, write g_yh/g_yl ----
    {
        float inv0 = 1.0f / l0;
        float inv1 = 1.0f / l1;
        int b = bh / NH, h = bh % NH;
        size_t off0 = ((size_t)(b * TT + rowg))  * DM + h * DH;
        size_t off1 = ((size_t)(b * TT + rowg8)) * DM + h * DH;
#pragma unroll
        for (int nt = 0; nt < 8; nt++) {
            int d = nt * 8 + 2 * t;
            uint32_t hi, lo;
            packsplit_h(o[nt][0] * inv0, o[nt][1] * inv0, hi, lo);
            *(uint32_t*)(g_yh + off0 + d) = hi;
            *(uint32_t*)(g_yl + off0 + d) = lo;
            packsplit_h(o[nt][2] * inv1, o[nt][3] * inv1, hi, lo);
            *(uint32_t*)(g_yh + off1 + d) = hi;
            *(uint32_t*)(g_yl + off1 + d) = lo;
        }
    }
}

// ---------------- launch -----------------------------------------------------------
extern "C" void kernel_launch(void* const* d_in, const int* in_sizes, int n_in,
                              void* d_out, int out_size)
{
    const float *x = nullptr, *wa = nullptr, *ba = nullptr, *wp = nullptr, *bp = nullptr;
    for (int divi = 0; divi < 2; divi++) {
        long long div = (divi == 0) ? 1 : 4;
        const float *tx=nullptr,*twa=nullptr,*tba=nullptr,*twp=nullptr,*tbp=nullptr;
        for (int i = 0; i < n_in; i++) {
            long long s = (long long)in_sizes[i] / div;
            if      (s == 3145728) tx  = (const float*)d_in[i];
            else if (s == 1769472) twa = (const float*)d_in[i];
            else if (s == 589824)  twp = (const float*)d_in[i];
            else if (s == 2304)    tba = (const float*)d_in[i];
            else if (s == 768)     tbp = (const float*)d_in[i];
        }
        if (tx && twa && tba && twp && tbp) { x=tx; wa=twa; ba=tba; wp=twp; bp=tbp; break; }
    }
    if (!(x && wa && ba && wp && bp)) return;

    float* out = (float*)d_out;

    cudaFuncSetAttribute(gemm_h<1>, cudaFuncAttributeMaxDynamicSharedMemorySize, GEMM_SMEM);
    cudaFuncSetAttribute(gemm_h<2>, cudaFuncAttributeMaxDynamicSharedMemorySize, GEMM_SMEM);
    cudaFuncSetAttribute(attn_reg,  cudaFuncAttributeMaxDynamicSharedMemorySize, ATT_SMEM);

    // 0) split x to f16 hi/lo; transpose weights to single f16
    split_x<<<MROWS * DM / (256 * 8), 256>>>(x);
    {
        dim3 gw(NQKV / 32, DM / 32);   // (72, 24)
        splitT_w<0><<<gw, 256>>>(wa, NQKV);
        dim3 gp(DM / 32, DM / 32);     // (24, 24)
        splitT_w<1><<<gp, 256>>>(wp, DM);
    }
    // 1) QKV projection (2-term f16, pipelined)
    {
        dim3 grid(NQKV / GN, MROWS / GM);   // (18, 32)
        gemm_h<1><<<grid, 256, GEMM_SMEM>>>(ba, nullptr, NQKV);
    }
    // 2) causal attention (128 queries/block, pipelined K/V)
    {
        dim3 grid(TT / QROWS, BB * NH);     // (16, 24)
        attn_reg<<<grid, 256, ATT_SMEM>>>();
    }
    // 3) output projection (2-term f16, pipelined)
    {
        dim3 grid(DM / GN, MROWS / GM);     // (6, 32)
        gemm_h<2><<<grid, 256, GEMM_SMEM>>>(bp, out, DM);
    }
}

// round 17
// speedup vs baseline: 1.4043x; 1.4043x over previous
#include <cuda_runtime.h>
#include <cuda_fp16.h>
#include <cstdint>

#define BB 2
#define TT 2048
#define NH 12
#define DH 64
#define DM 768
#define NQKV (3*DM)
#define MROWS (BB*TT)   // 4096

// Scratch (allocation-free). NOTE: never pass these symbols from host code —
// GB300 ATS silently resolves the host shadow address (reads zeros).
__device__ __align__(16) __half g_x  [(size_t)MROWS*DM];    // x single f16
__device__ __align__(16) __half g_wat[(size_t)NQKV*DM];     // [2304,768] transposed, f16
__device__ __align__(16) __half g_wpt[(size_t)DM*DM];       // [768,768]  transposed, f16
__device__ __align__(16) __half g_qh[(size_t)BB*NH*TT*DH];  // q hi (scaled)
__device__ __align__(16) __half g_ql[(size_t)BB*NH*TT*DH];  // q lo
__device__ __align__(16) __half g_k [(size_t)BB*NH*TT*DH];  // k single f16
__device__ __align__(16) __half g_vt[(size_t)BB*NH*DH*TT];  // v single f16 [B,H,D,T]
__device__ __align__(16) __half g_y [(size_t)MROWS*DM];     // y single f16

// ---------------- helpers ----------------------------------------------------------
__device__ __forceinline__ void split_h(float v, __half& hi, __half& lo)
{
    hi = __float2half_rn(v);
    lo = __float2half_rn(v - __half2float(hi));
}

__device__ __forceinline__ void mma16816h(float* c, uint32_t a0, uint32_t a1,
                                          uint32_t a2, uint32_t a3,
                                          uint32_t b0, uint32_t b1)
{
    asm volatile(
        "mma.sync.aligned.m16n8k16.row.col.f32.f16.f16.f32 "
        "{%0,%1,%2,%3}, {%4,%5,%6,%7}, {%8,%9}, {%0,%1,%2,%3};\n"
        : "+f"(c[0]), "+f"(c[1]), "+f"(c[2]), "+f"(c[3])
        : "r"(a0), "r"(a1), "r"(a2), "r"(a3), "r"(b0), "r"(b1));
}

__device__ __forceinline__ uint32_t lds32(const __half* p)
{
    return *(const uint32_t*)p;
}

__device__ __forceinline__ void cp16(void* smem_ptr, const void* gptr)
{
    uint32_t sa = (uint32_t)__cvta_generic_to_shared(smem_ptr);
    asm volatile("cp.async.cg.shared.global [%0], [%1], 16;\n"
                 :: "r"(sa), "l"(gptr));
}
#define CP_COMMIT() asm volatile("cp.async.commit_group;\n" ::: "memory")
#define CP_WAIT1()  asm volatile("cp.async.wait_group 1;\n" ::: "memory")
#define CP_WAIT0()  asm volatile("cp.async.wait_group 0;\n" ::: "memory")

// ---------------- input conversion kernels ------------------------------------------
__global__ __launch_bounds__(256) void conv_x(const float* __restrict__ x)
{
    size_t i = ((size_t)blockIdx.x * 256 + threadIdx.x) * 8;
    float4 v0 = *(const float4*)(x + i);
    float4 v1 = *(const float4*)(x + i + 4);
    __half h[8] = {
        __float2half_rn(v0.x), __float2half_rn(v0.y),
        __float2half_rn(v0.z), __float2half_rn(v0.w),
        __float2half_rn(v1.x), __float2half_rn(v1.y),
        __float2half_rn(v1.z), __float2half_rn(v1.w)};
    *(uint4*)(g_x + i) = *(uint4*)h;
}

// Transpose weight [768, N] -> [N, 768] single f16.  W=0: w_attn, W=1: w_proj
template <int W>
__global__ __launch_bounds__(256) void splitT_w(const float* __restrict__ w, int N)
{
    __shared__ float ts[32][33];
    const int tx = threadIdx.x & 31, ty = threadIdx.x >> 5;  // 32 x 8
    const int n0 = blockIdx.x * 32, k0 = blockIdx.y * 32;
#pragma unroll
    for (int i = 0; i < 4; i++) {
        int ky = ty + i * 8;
        ts[ky][tx] = w[(size_t)(k0 + ky) * N + n0 + tx];
    }
    __syncthreads();
    __half* th = (W == 0) ? g_wat : g_wpt;
#pragma unroll
    for (int i = 0; i < 4; i++) {
        int r = ty + i * 8;
        th[(size_t)(n0 + r) * DM + k0 + tx] = __float2half_rn(ts[tx][r]);
    }
}

// ---------------- 1-term f16 raw-mma GEMM, cp.async double-buffered -----------------
// C[M,N] = A*B^T + bias; A single f16, B single f16 (transposed [N,K]).
// Block tile 128x128xK32, 256 threads (8 warps, 4m x 2n, warp tile 32x64).
#define GM 128
#define GN 128
#define GKT 32
#define GLD 40
#define GCN 68
#define GST (2*GM*GLD)                 // halves per stage (A+B) = 10240
#define GEMM_SMEM (2*GST*2 > GM*GCN*4 ? 2*GST*2 : GM*GCN*4)   // 40960 B

template <int MODE>
__global__ __launch_bounds__(256) void gemm_h(const float* __restrict__ bias,
                                              float* __restrict__ Cout, int N)
{
    constexpr int K = DM;
    const __half* __restrict__ Ag = (MODE == 1) ? g_x : g_y;
    const __half* __restrict__ Bg = (MODE == 1) ? g_wat : g_wpt;

    extern __shared__ char gsm[];
    __half* ST = (__half*)gsm;
    float*  Cs = (float*)gsm;

    const int tid  = threadIdx.x;
    const int warp = tid >> 5, lane = tid & 31;
    const int g = lane >> 2, t = lane & 3;
    const int m0 = (warp & 3) * 32, wn = warp >> 2, n0 = wn * 64;
    const int bm = blockIdx.y * GM, bn = blockIdx.x * GN;

    const int ldr  = tid >> 2;            // 0..63
    const int ldc8 = (tid & 3) * 8;       // 0,8,16,24

    auto issue = [&](int k0, int s) {
        __half* AS = ST + s * GST;
        __half* BS = AS + GM * GLD;
#pragma unroll
        for (int i = 0; i < 2; i++) {
            int r = ldr + i * 64;
            cp16(AS + r * GLD + ldc8, Ag + (size_t)(bm + r) * K + k0 + ldc8);
            cp16(BS + r * GLD + ldc8, Bg + (size_t)(bn + r) * K + k0 + ldc8);
        }
    };

    float acc[2][8][4] = {};

    issue(0, 0);
    CP_COMMIT();

    const int nk = K / GKT;   // 24
    for (int kt = 0; kt < nk; kt++) {
        if (kt + 1 < nk) { issue((kt + 1) * GKT, (kt + 1) & 1); CP_COMMIT(); CP_WAIT1(); }
        else             { CP_WAIT0(); }
        __syncthreads();

        const __half* AS = ST + (kt & 1) * GST;
        const __half* BS = AS + GM * GLD;

#pragma unroll
        for (int kc = 0; kc < 2; kc++) {
            const int dlo = kc * 16 + 2 * t;
            uint32_t aF[2][4];
#pragma unroll
            for (int mi = 0; mi < 2; mi++) {
                int r0 = m0 + mi * 16 + g, r1 = r0 + 8;
                aF[mi][0] = lds32(AS + r0 * GLD + dlo);
                aF[mi][1] = lds32(AS + r1 * GLD + dlo);
                aF[mi][2] = lds32(AS + r0 * GLD + dlo + 8);
                aF[mi][3] = lds32(AS + r1 * GLD + dlo + 8);
            }
#pragma unroll
            for (int ni = 0; ni < 8; ni++) {
                int rn = n0 + ni * 8 + g;
                uint32_t b0 = lds32(BS + rn * GLD + dlo);
                uint32_t b1 = lds32(BS + rn * GLD + dlo + 8);
#pragma unroll
                for (int mi = 0; mi < 2; mi++)
                    mma16816h(acc[mi][ni], aF[mi][0], aF[mi][1], aF[mi][2], aF[mi][3], b0, b1);
            }
        }
        __syncthreads();
    }

    // Epilogue: two 64-col passes through Cs
#pragma unroll
    for (int pass = 0; pass < 2; pass++) {
        __syncthreads();
        if (wn == pass) {
#pragma unroll
            for (int mi = 0; mi < 2; mi++)
#pragma unroll
                for (int ni = 0; ni < 8; ni++) {
                    int r = m0 + mi * 16 + g, c = ni * 8 + 2 * t;
                    *(float2*)&Cs[r * GCN + c]       = make_float2(acc[mi][ni][0], acc[mi][ni][1]);
                    *(float2*)&Cs[(r + 8) * GCN + c] = make_float2(acc[mi][ni][2], acc[mi][ni][3]);
                }
        }
        __syncthreads();

        const int nwin = bn + pass * 64;
        if (MODE == 2) {
#pragma unroll
            for (int it = 0; it < 32; it++) {
                int idx = tid + it * 256;
                int r = idx >> 6;
                int n_loc = idx & 63;
                Cout[(size_t)(bm + r) * N + nwin + n_loc] = Cs[r * GCN + n_loc] + bias[nwin + n_loc];
            }
        } else {
            const int which = nwin / DM;
            const int hd    = nwin % DM;
            const int h     = hd / DH;
            const int b     = bm / TT;
            const int t0    = bm % TT;
            const int bh    = b * NH + h;

            if (which == 2) {
#pragma unroll
                for (int it = 0; it < 4; it++) {
                    int cid = tid + it * 256;
                    int d   = cid >> 4;
                    int tc  = (cid & 15) * 8;
                    float bval = bias[nwin + d];
                    __half hb[8];
#pragma unroll
                    for (int j = 0; j < 8; j++)
                        hb[j] = __float2half_rn(Cs[(tc + j) * GCN + d] + bval);
                    *(uint4*)(g_vt + ((size_t)bh * DH + d) * TT + t0 + tc) = *(uint4*)hb;
                }
            } else if (which == 1) {
#pragma unroll
                for (int it = 0; it < 4; it++) {
                    int cid = tid + it * 256;
                    int r   = cid >> 3;
                    int c8  = (cid & 7) * 8;
                    __half hb[8];
#pragma unroll
                    for (int j = 0; j < 8; j++)
                        hb[j] = __float2half_rn(Cs[r * GCN + c8 + j] + bias[nwin + c8 + j]);
                    *(uint4*)(g_k + ((size_t)bh * TT + t0 + r) * DH + c8) = *(uint4*)hb;
                }
            } else {
#pragma unroll
                for (int it = 0; it < 4; it++) {
                    int cid = tid + it * 256;
                    int r   = cid >> 3;
                    int c8  = (cid & 7) * 8;
                    __half hb[8], lb[8];
#pragma unroll
                    for (int j = 0; j < 8; j++) {
                        float v = (Cs[r * GCN + c8 + j] + bias[nwin + c8 + j]) * 0.125f;
                        split_h(v, hb[j], lb[j]);
                    }
                    size_t dst = ((size_t)bh * TT + t0 + r) * DH + c8;
                    *(uint4*)(g_qh + dst) = *(uint4*)hb;
                    *(uint4*)(g_ql + dst) = *(uint4*)lb;
                }
            }
        }
    }
}

// ---------------- Flash attention: 64 q/block, P single f16, K/V pipelined ----------
#define LOG2E 1.4426950408889634f
#define LDSB 72
#define AST (2*64*LDSB)                     // halves per K/V stage = 9216
#define ATT_SMEM ((2*64*LDSB + 2*AST) * 2)  // 55296 B

__device__ __forceinline__ float fexp2(float t)   // t <= 0; returns 2^t
{
    t = fmaxf(t, -126.f);
    float fl = floorf(t);
    float x = (t - fl) * 0.69314718056f;
    float p = 1.f + x*(1.f + x*(0.5f + x*(0.16666667f + x*(0.041666667f
              + x*(0.0083333333f + x*0.0013888889f)))));
    return __int_as_float(__float_as_int(p) + ((int)fl << 23));
}

__global__ __launch_bounds__(128) void attn_reg()
{
    extern __shared__ __half smb[];
    __half* QH = smb;
    __half* QL = QH + 64*LDSB;
    __half* S0 = QL + 64*LDSB;     // K/V stage base

    const int bh   = blockIdx.y;
    const int qt   = gridDim.x - 1 - blockIdx.x;  // heavy first
    const int tid  = threadIdx.x;
    const int warp = tid >> 5;
    const int lane = tid & 31;
    const int g    = lane >> 2;
    const int t    = lane & 3;
    const int q0   = qt * 64;

    const __half* gqh = g_qh + (size_t)bh * TT * DH;
    const __half* gql = g_ql + (size_t)bh * TT * DH;
    const __half* gk  = g_k  + (size_t)bh * TT * DH;
    const __half* gv  = g_vt + (size_t)bh * DH * TT;

    auto issue_kv = [&](int kt, int s) {
        __half* KH = S0 + s * AST;
        __half* VT = KH + 64 * LDSB;
#pragma unroll
        for (int it = 0; it < 4; it++) {
            int cid = tid + it * 128;
            int r   = cid >> 3;
            int c8  = (cid & 7) * 8;
            cp16(KH + r * LDSB + c8, gk + (size_t)(kt*64 + r) * DH + c8);
            cp16(VT + r * LDSB + c8, gv + (size_t)r * TT + kt*64 + c8);
        }
    };

    issue_kv(0, 0);
    CP_COMMIT();

#pragma unroll
    for (int it = 0; it < 4; it++) {
        int cid = tid + it * 128;
        int r   = cid >> 3;
        int c8  = (cid & 7) * 8;
        *(uint4*)(QH + r * LDSB + c8) = *(const uint4*)(gqh + (size_t)(q0 + r) * DH + c8);
        *(uint4*)(QL + r * LDSB + c8) = *(const uint4*)(gql + (size_t)(q0 + r) * DH + c8);
    }
    __syncthreads();

    // Hoist Q fragments into registers (block-invariant across kt)
    uint32_t qfh[4][4], qfl[4][4];
    {
        const int qrow = warp * 16 + g;
#pragma unroll
        for (int kc = 0; kc < 4; kc++) {
            const int dlo = kc * 16 + 2 * t;
            qfh[kc][0] = lds32(QH + qrow * LDSB + dlo);
            qfh[kc][1] = lds32(QH + (qrow + 8) * LDSB + dlo);
            qfh[kc][2] = lds32(QH + qrow * LDSB + dlo + 8);
            qfh[kc][3] = lds32(QH + (qrow + 8) * LDSB + dlo + 8);
            qfl[kc][0] = lds32(QL + qrow * LDSB + dlo);
            qfl[kc][1] = lds32(QL + (qrow + 8) * LDSB + dlo);
            qfl[kc][2] = lds32(QL + qrow * LDSB + dlo + 8);
            qfl[kc][3] = lds32(QL + (qrow + 8) * LDSB + dlo + 8);
        }
    }

    float o[8][4];
#pragma unroll
    for (int nt = 0; nt < 8; nt++)
#pragma unroll
        for (int e = 0; e < 4; e++) o[nt][e] = 0.f;
    float m0 = -1e30f, m1 = -1e30f, l0 = 0.f, l1 = 0.f;

    const int rowg  = q0 + warp * 16 + g;
    const int rowg8 = rowg + 8;

    for (int kt = 0; kt <= qt; kt++) {
        if (kt + 1 <= qt) { issue_kv(kt + 1, (kt + 1) & 1); CP_COMMIT(); CP_WAIT1(); }
        else              { CP_WAIT0(); }
        __syncthreads();

        const __half* KH = S0 + (kt & 1) * AST;
        const __half* VT = KH + 64 * LDSB;

        // ---- S = Q K^T (Q exact hi/lo, K single f16) ----
        float s[8][4];
#pragma unroll
        for (int nt = 0; nt < 8; nt++)
#pragma unroll
            for (int e = 0; e < 4; e++) s[nt][e] = 0.f;

#pragma unroll
        for (int kc = 0; kc < 4; kc++) {
            const int dlo = kc * 16 + 2 * t;
#pragma unroll
            for (int nt = 0; nt < 8; nt++) {
                const int krow = nt * 8 + g;
                uint32_t b0 = lds32(KH + krow * LDSB + dlo);
                uint32_t b1 = lds32(KH + krow * LDSB + dlo + 8);
                mma16816h(s[nt], qfh[kc][0], qfh[kc][1], qfh[kc][2], qfh[kc][3], b0, b1);
                mma16816h(s[nt], qfl[kc][0], qfl[kc][1], qfl[kc][2], qfl[kc][3], b0, b1);
            }
        }

        // ---- causal mask on the diagonal tile ----
        if (kt == qt) {
#pragma unroll
            for (int nt = 0; nt < 8; nt++) {
                int c0 = kt * 64 + nt * 8 + 2 * t;
                if (c0     > rowg)  s[nt][0] = -1e30f;
                if (c0 + 1 > rowg)  s[nt][1] = -1e30f;
                if (c0     > rowg8) s[nt][2] = -1e30f;
                if (c0 + 1 > rowg8) s[nt][3] = -1e30f;
            }
        }

        // ---- online softmax ----
        float tmax0 = -1e30f, tmax1 = -1e30f;
#pragma unroll
        for (int nt = 0; nt < 8; nt++) {
            tmax0 = fmaxf(tmax0, fmaxf(s[nt][0], s[nt][1]));
            tmax1 = fmaxf(tmax1, fmaxf(s[nt][2], s[nt][3]));
        }
        tmax0 = fmaxf(tmax0, __shfl_xor_sync(0xffffffff, tmax0, 1));
        tmax0 = fmaxf(tmax0, __shfl_xor_sync(0xffffffff, tmax0, 2));
        tmax1 = fmaxf(tmax1, __shfl_xor_sync(0xffffffff, tmax1, 1));
        tmax1 = fmaxf(tmax1, __shfl_xor_sync(0xffffffff, tmax1, 2));

        float mnew0 = fmaxf(m0, tmax0);
        float mnew1 = fmaxf(m1, tmax1);
        float f0 = fexp2((m0 - mnew0) * LOG2E);
        float f1 = fexp2((m1 - mnew1) * LOG2E);

        // P packed to single f16; l sums the ROUNDED p's (common-mode cancels)
        uint32_t pa[4][4];
        float ls0 = 0.f, ls1 = 0.f;
#pragma unroll
        for (int kc = 0; kc < 4; kc++) {
            float p00 = fexp2((s[2*kc][0]   - mnew0) * LOG2E);
            float p01 = fexp2((s[2*kc][1]   - mnew0) * LOG2E);
            float p02 = fexp2((s[2*kc][2]   - mnew1) * LOG2E);
            float p03 = fexp2((s[2*kc][3]   - mnew1) * LOG2E);
            float p10 = fexp2((s[2*kc+1][0] - mnew0) * LOG2E);
            float p11 = fexp2((s[2*kc+1][1] - mnew0) * LOG2E);
            float p12 = fexp2((s[2*kc+1][2] - mnew1) * LOG2E);
            float p13 = fexp2((s[2*kc+1][3] - mnew1) * LOG2E);
            __half2 h0 = __floats2half2_rn(p00, p01);
            __half2 h1 = __floats2half2_rn(p02, p03);
            __half2 h2 = __floats2half2_rn(p10, p11);
            __half2 h3 = __floats2half2_rn(p12, p13);
            pa[kc][0] = *(uint32_t*)&h0;
            pa[kc][1] = *(uint32_t*)&h1;
            pa[kc][2] = *(uint32_t*)&h2;
            pa[kc][3] = *(uint32_t*)&h3;
            float2 u0 = __half22float2(h0), u1 = __half22float2(h1);
            float2 u2 = __half22float2(h2), u3 = __half22float2(h3);
            ls0 += (u0.x + u0.y) + (u2.x + u2.y);
            ls1 += (u1.x + u1.y) + (u3.x + u3.y);
        }
        ls0 += __shfl_xor_sync(0xffffffff, ls0, 1);
        ls0 += __shfl_xor_sync(0xffffffff, ls0, 2);
        ls1 += __shfl_xor_sync(0xffffffff, ls1, 1);
        ls1 += __shfl_xor_sync(0xffffffff, ls1, 2);

        l0 = l0 * f0 + ls0;  m0 = mnew0;
        l1 = l1 * f1 + ls1;  m1 = mnew1;

#pragma unroll
        for (int nt = 0; nt < 8; nt++) {
            o[nt][0] *= f0; o[nt][1] *= f0;
            o[nt][2] *= f1; o[nt][3] *= f1;
        }

        // ---- O += P * V (both single f16) ----
#pragma unroll
        for (int kc = 0; kc < 4; kc++) {
            const int klo = kc * 16 + 2 * t;
#pragma unroll
            for (int nt = 0; nt < 8; nt++) {
                const int drow = nt * 8 + g;
                uint32_t v0 = lds32(VT + drow * LDSB + klo);
                uint32_t v1 = lds32(VT + drow * LDSB + klo + 8);
                mma16816h(o[nt], pa[kc][0], pa[kc][1], pa[kc][2], pa[kc][3], v0, v1);
            }
        }
        __syncthreads();
    }

    // ---- epilogue: normalize, write y single f16 ----
    {
        float inv0 = 1.0f / l0;
        float inv1 = 1.0f / l1;
        int b = bh / NH, h = bh % NH;
        size_t off0 = ((size_t)(b * TT + rowg))  * DM + h * DH;
        size_t off1 = ((size_t)(b * TT + rowg8)) * DM + h * DH;
#pragma unroll
        for (int nt = 0; nt < 8; nt++) {
            int d = nt * 8 + 2 * t;
            __half2 h0 = __floats2half2_rn(o[nt][0] * inv0, o[nt][1] * inv0);
            __half2 h1 = __floats2half2_rn(o[nt][2] * inv1, o[nt][3] * inv1);
            *(uint32_t*)(g_y + off0 + d) = *(uint32_t*)&h0;
            *(uint32_t*)(g_y + off1 + d) = *(uint32_t*)&h1;
        }
    }
}

// ---------------- launch -----------------------------------------------------------
extern "C" void kernel_launch(void* const* d_in, const int* in_sizes, int n_in,
                              void* d_out, int out_size)
{
    const float *x = nullptr, *wa = nullptr, *ba = nullptr, *wp = nullptr, *bp = nullptr;
    for (int divi = 0; divi < 2; divi++) {
        long long div = (divi == 0) ? 1 : 4;
        const float *tx=nullptr,*twa=nullptr,*tba=nullptr,*twp=nullptr,*tbp=nullptr;
        for (int i = 0; i < n_in; i++) {
            long long s = (long long)in_sizes[i] / div;
            if      (s == 3145728) tx  = (const float*)d_in[i];
            else if (s == 1769472) twa = (const float*)d_in[i];
            else if (s == 589824)  twp = (const float*)d_in[i];
            else if (s == 2304)    tba = (const float*)d_in[i];
            else if (s == 768)     tbp = (const float*)d_in[i];
        }
        if (tx && twa && tba && twp && tbp) { x=tx; wa=twa; ba=tba; wp=twp; bp=tbp; break; }
    }
    if (!(x && wa && ba && wp && bp)) return;

    float* out = (float*)d_out;

    cudaFuncSetAttribute(gemm_h<1>, cudaFuncAttributeMaxDynamicSharedMemorySize, GEMM_SMEM);
    cudaFuncSetAttribute(gemm_h<2>, cudaFuncAttributeMaxDynamicSharedMemorySize, GEMM_SMEM);
    cudaFuncSetAttribute(attn_reg,  cudaFuncAttributeMaxDynamicSharedMemorySize, ATT_SMEM);

    // 0) convert x to f16; transpose weights to single f16
    conv_x<<<MROWS * DM / (256 * 8), 256>>>(x);
    {
        dim3 gw(NQKV / 32, DM / 32);   // (72, 24)
        splitT_w<0><<<gw, 256>>>(wa, NQKV);
        dim3 gp(DM / 32, DM / 32);     // (24, 24)
        splitT_w<1><<<gp, 256>>>(wp, DM);
    }
    // 1) QKV projection (1-term f16, pipelined)
    {
        dim3 grid(NQKV / GN, MROWS / GM);   // (18, 32)
        gemm_h<1><<<grid, 256, GEMM_SMEM>>>(ba, nullptr, NQKV);
    }
    // 2) causal attention (64 q/block, single-f16 P)
    {
        dim3 grid(TT / 64, BB * NH);        // (32, 24)
        attn_reg<<<grid, 128, ATT_SMEM>>>();
    }
    // 3) output projection (1-term f16, pipelined)
    {
        dim3 grid(DM / GN, MROWS / GM);     // (6, 32)
        gemm_h<2><<<grid, 256, GEMM_SMEM>>>(bp, out, DM);
    }
}